// round 1
// baseline (speedup 1.0000x reference)
#include <cuda_runtime.h>
#include <cstdint>
#include <math.h>

#define N_NODES   100000
#define N_EDGES   1600000
#define HID       128
#define N_CLASSES 18
#define N_CENT    2
#define N_GRAPHS  512

// ---------------- scratch (static device memory; no allocs allowed) ----------
__device__ float g_hn [N_NODES * HID];     // h * dinv  (gather source)
__device__ float g_cur[N_NODES * HID];     // layer output / next layer input
__device__ float g_dinv[N_NODES];
__device__ int   g_deg [N_NODES];          // in-degree (w/o self loop)
__device__ int   g_off [N_NODES];          // CSR row offsets
__device__ int   g_cursor[N_NODES];        // mutable cursor for CSR fill
__device__ int   g_src [N_EDGES];
__device__ int   g_dst [N_EDGES];
__device__ int   g_csr [N_EDGES];          // src indices grouped by dst
__device__ int   g_gcnt[N_GRAPHS];
__device__ int   g_goff[N_GRAPHS + 1];
__device__ float g_pool[N_GRAPHS * HID];
__device__ int   g_eis64;
__device__ int   g_bis64;

// ---------------- setup kernels ---------------------------------------------
__global__ void zero_kernel() {
    int i = blockIdx.x * blockDim.x + threadIdx.x;
    if (i < N_NODES)  g_deg[i]  = 0;
    if (i < N_GRAPHS) g_gcnt[i] = 0;
}

// Detect whether index buffers are int64 or int32 (JAX may silently downcast).
// For int64 (values >=0, < 2^31), every odd 32-bit word is 0.
// Sampled positions are chosen so the int32 interpretation is (a.s.) nonzero.
__global__ void detect_kernel(const void* ebuf, const void* bbuf) {
    __shared__ int nz_e, nz_b;
    if (threadIdx.x == 0) { nz_e = 0; nz_b = 0; }
    __syncthreads();
    const int* e32 = (const int*)ebuf;
    const int* b32 = (const int*)bbuf;
    int i = threadIdx.x;                       // 256 threads
    long long ke = 1000 + (long long)i * 997;  // word 2*ke+1 < 3.2M either way
    if (e32[2 * ke + 1] != 0) atomicAdd(&nz_e, 1);
    long long kb = 20000 + (long long)i * 117; // word 2*kb+1 < 100000 (int32 safe)
    if (b32[2 * kb + 1] != 0) atomicAdd(&nz_b, 1);
    __syncthreads();
    if (threadIdx.x == 0) { g_eis64 = (nz_e < 8); g_bis64 = (nz_b < 8); }
}

__global__ void convert_edges(const void* ebuf) {
    int e = blockIdx.x * blockDim.x + threadIdx.x;
    if (e >= N_EDGES) return;
    int s, d;
    if (g_eis64) {
        const long long* p = (const long long*)ebuf;
        s = (int)p[e]; d = (int)p[N_EDGES + e];
    } else {
        const int* p = (const int*)ebuf;
        s = p[e]; d = p[N_EDGES + e];
    }
    g_src[e] = s; g_dst[e] = d;
    atomicAdd(&g_deg[d], 1);
}

__global__ void convert_batch(const void* bbuf) {
    int n = blockIdx.x * blockDim.x + threadIdx.x;
    if (n >= N_NODES) return;
    int b;
    if (g_bis64) b = (int)((const long long*)bbuf)[n];
    else         b = ((const int*)bbuf)[n];
    atomicAdd(&g_gcnt[b], 1);
}

// single-block scan over node degrees -> CSR offsets + cursor copy
#define SCAN_T 1024
#define CHUNK  98   // 1024*98 >= 100000
__global__ void node_scan_kernel() {
    __shared__ int wsum[32];
    int tid = threadIdx.x, lane = tid & 31, wid = tid >> 5;
    int start = tid * CHUNK;
    int csum = 0;
    for (int i = 0; i < CHUNK; i++) {
        int idx = start + i;
        if (idx < N_NODES) csum += g_deg[idx];
    }
    int v = csum;
    #pragma unroll
    for (int o = 1; o < 32; o <<= 1) { int t = __shfl_up_sync(0xffffffffu, v, o); if (lane >= o) v += t; }
    if (lane == 31) wsum[wid] = v;
    __syncthreads();
    if (wid == 0) {
        int w = wsum[lane];
        #pragma unroll
        for (int o = 1; o < 32; o <<= 1) { int t = __shfl_up_sync(0xffffffffu, w, o); if (lane >= o) w += t; }
        wsum[lane] = w;
    }
    __syncthreads();
    int run = v - csum + (wid > 0 ? wsum[wid - 1] : 0);
    for (int i = 0; i < CHUNK; i++) {
        int idx = start + i;
        if (idx < N_NODES) {
            g_off[idx] = run;
            g_cursor[idx] = run;
            run += g_deg[idx];
        }
    }
}

__global__ void graph_scan_kernel() {   // 1 block, 512 threads
    __shared__ int sh[N_GRAPHS];
    int t = threadIdx.x;
    sh[t] = g_gcnt[t];
    __syncthreads();
    for (int o = 1; o < N_GRAPHS; o <<= 1) {
        int v = (t >= o) ? sh[t - o] : 0;
        __syncthreads();
        sh[t] += v;
        __syncthreads();
    }
    g_goff[t + 1] = sh[t];
    if (t == 0) g_goff[0] = 0;
}

__global__ void csr_fill_kernel() {
    int e = blockIdx.x * blockDim.x + threadIdx.x;
    if (e >= N_EDGES) return;
    int d = g_dst[e];
    int pos = atomicAdd(&g_cursor[d], 1);
    g_csr[pos] = g_src[e];
}

__global__ void dinv_kernel() {
    int i = blockIdx.x * blockDim.x + threadIdx.x;
    if (i < N_NODES) g_dinv[i] = rsqrtf((float)g_deg[i] + 1.0f);
}

// ---------------- GEMM: hn = (X @ W) * dinv[row] ----------------------------
// tile: 64 rows x 128 cols, 256 threads, each thread 8 rows x 4 cols
__global__ void gemm_kernel(const float* __restrict__ Xin, const float* __restrict__ W, int n) {
    extern __shared__ float sm[];
    float* sW = sm;               // 128*128
    float* sX = sm + 128 * 128;   // 64*128
    const float* X = Xin ? Xin : g_cur;
    int tid = threadIdx.x;

    float4* sW4 = (float4*)sW;
    const float4* W4 = (const float4*)W;
    for (int i = tid; i < 128 * 32; i += 256) sW4[i] = W4[i];

    int r0 = blockIdx.x * 64;
    float4* sX4 = (float4*)sX;
    for (int i = tid; i < 64 * 32; i += 256) {
        int r = i >> 5, c4 = i & 31;
        int row = r0 + r;
        float4 v = make_float4(0.f, 0.f, 0.f, 0.f);
        if (row < n) v = ((const float4*)X)[(size_t)row * 32 + c4];
        sX4[i] = v;
    }
    __syncthreads();

    int cg = tid & 31;   // cols cg*4..cg*4+3
    int rg = tid >> 5;   // rows rg*8..rg*8+7
    float4 acc[8];
    #pragma unroll
    for (int i = 0; i < 8; i++) acc[i] = make_float4(0.f, 0.f, 0.f, 0.f);

    for (int k = 0; k < 128; k++) {
        float4 wv = sW4[k * 32 + cg];
        #pragma unroll
        for (int i = 0; i < 8; i++) {
            float a = sX[(rg * 8 + i) * 128 + k];
            acc[i].x = fmaf(a, wv.x, acc[i].x);
            acc[i].y = fmaf(a, wv.y, acc[i].y);
            acc[i].z = fmaf(a, wv.z, acc[i].z);
            acc[i].w = fmaf(a, wv.w, acc[i].w);
        }
    }

    float4* hn4 = (float4*)g_hn;
    #pragma unroll
    for (int i = 0; i < 8; i++) {
        int row = r0 + rg * 8 + i;
        if (row < n) {
            float di = g_dinv[row];
            float4 o = make_float4(acc[i].x * di, acc[i].y * di, acc[i].z * di, acc[i].w * di);
            hn4[(size_t)row * 32 + cg] = o;
        }
    }
}

// ---------------- aggregate: out = dinv[d]*(hn[d]+sum hn[src]) + b (+relu) --
__global__ void aggregate_kernel(const float* __restrict__ bias, int do_relu) {
    int w = (blockIdx.x * blockDim.x + threadIdx.x) >> 5;
    if (w >= N_NODES) return;
    int lane = threadIdx.x & 31;
    const float4* hn4 = (const float4*)g_hn;

    float4 sum = hn4[(size_t)w * 32 + lane];   // self loop: + hn[d]
    int base = g_off[w];
    int cnt  = g_deg[w];
    int j = 0;
    for (; j + 4 <= cnt; j += 4) {
        int s0 = g_csr[base + j + 0];
        int s1 = g_csr[base + j + 1];
        int s2 = g_csr[base + j + 2];
        int s3 = g_csr[base + j + 3];
        float4 v0 = hn4[(size_t)s0 * 32 + lane];
        float4 v1 = hn4[(size_t)s1 * 32 + lane];
        float4 v2 = hn4[(size_t)s2 * 32 + lane];
        float4 v3 = hn4[(size_t)s3 * 32 + lane];
        sum.x += v0.x + v1.x + v2.x + v3.x;
        sum.y += v0.y + v1.y + v2.y + v3.y;
        sum.z += v0.z + v1.z + v2.z + v3.z;
        sum.w += v0.w + v1.w + v2.w + v3.w;
    }
    for (; j < cnt; j++) {
        int s = g_csr[base + j];
        float4 v = hn4[(size_t)s * 32 + lane];
        sum.x += v.x; sum.y += v.y; sum.z += v.z; sum.w += v.w;
    }

    float di = g_dinv[w];
    float4 bv = ((const float4*)bias)[lane];
    float4 o = make_float4(sum.x * di + bv.x, sum.y * di + bv.y,
                           sum.z * di + bv.z, sum.w * di + bv.w);
    if (do_relu) {
        o.x = fmaxf(o.x, 0.f); o.y = fmaxf(o.y, 0.f);
        o.z = fmaxf(o.z, 0.f); o.w = fmaxf(o.w, 0.f);
    }
    ((float4*)g_cur)[(size_t)w * 32 + lane] = o;
}

// ---------------- pooling + centroid head ----------------------------------
__global__ void pool_kernel() {   // block per graph, 128 threads
    int g = blockIdx.x, c = threadIdx.x;
    int s = g_goff[g], e = g_goff[g + 1];
    float sum = 0.f;
    for (int r = s; r < e; r++) sum += g_cur[(size_t)r * HID + c];
    float cntf = (float)(e - s);
    g_pool[g * HID + c] = sum / fmaxf(cntf, 1.0f);
}

__global__ void centroid_kernel(const float* __restrict__ cent,
                                const float* __restrict__ ac_temp,
                                float* __restrict__ out) {
    int b = blockIdx.x;
    int tid = threadIdx.x;            // 128 threads
    int lane = tid & 31, w = tid >> 5;
    __shared__ float sd[N_CLASSES * N_CENT];
    __shared__ float sg[HID];
    sg[tid] = g_pool[b * HID + tid];
    __syncthreads();
    for (int p = w; p < N_CLASSES * N_CENT; p += 4) {
        const float* cp = cent + p * HID;
        float s = 0.f;
        #pragma unroll
        for (int q = 0; q < 4; q++) {
            float d = cp[lane + q * 32] - sg[lane + q * 32];
            s = fmaf(d, d, s);
        }
        #pragma unroll
        for (int o = 16; o; o >>= 1) s += __shfl_xor_sync(0xffffffffu, s, o);
        if (lane == 0) sd[p] = sqrtf(s);
    }
    __syncthreads();
    if (tid == 0) {
        float mind = 1e30f;
        #pragma unroll
        for (int c = 0; c < N_CLASSES; c++) {
            float d = fminf(sd[2 * c], sd[2 * c + 1]);
            out[b * N_CLASSES + c] = -d;
            mind = fminf(mind, d);
        }
        // RUNNING_VAR == 0  =>  max_ac == RUNNING_MEAN == 1.0 exactly
        float accept = 1.0f - mind;
        float t = ac_temp[0];
        out[N_GRAPHS * N_CLASSES + b] = 1.0f / (1.0f + expf(-accept / t));
    }
}

// ---------------- launch ----------------------------------------------------
extern "C" void kernel_launch(void* const* d_in, const int* in_sizes, int n_in,
                              void* d_out, int out_size) {
    const float* x     = (const float*)d_in[0];
    const void*  edges = d_in[1];
    const void*  batch = d_in[2];
    const float* W1 = (const float*)d_in[3];
    const float* b1 = (const float*)d_in[4];
    const float* W2 = (const float*)d_in[5];
    const float* b2 = (const float*)d_in[6];
    const float* W3 = (const float*)d_in[7];
    const float* b3 = (const float*)d_in[8];
    const float* cent = (const float*)d_in[9];
    const float* ac_temp = (const float*)d_in[11];
    float* out = (float*)d_out;

    cudaFuncSetAttribute(gemm_kernel, cudaFuncAttributeMaxDynamicSharedMemorySize, 98304);

    int zb = (N_NODES + 255) / 256;
    zero_kernel<<<zb, 256>>>();
    detect_kernel<<<1, 256>>>(edges, batch);
    convert_edges<<<(N_EDGES + 255) / 256, 256>>>(edges);
    convert_batch<<<(N_NODES + 255) / 256, 256>>>(batch);
    node_scan_kernel<<<1, SCAN_T>>>();
    graph_scan_kernel<<<1, N_GRAPHS>>>();
    csr_fill_kernel<<<(N_EDGES + 255) / 256, 256>>>();
    dinv_kernel<<<(N_NODES + 255) / 256, 256>>>();

    int gemm_blocks = (N_NODES + 63) / 64;
    int agg_blocks  = (N_NODES * 32 + 255) / 256;

    // layer 1
    gemm_kernel<<<gemm_blocks, 256, 98304>>>(x, W1, N_NODES);
    aggregate_kernel<<<agg_blocks, 256>>>(b1, 1);
    // layer 2
    gemm_kernel<<<gemm_blocks, 256, 98304>>>(nullptr, W2, N_NODES);
    aggregate_kernel<<<agg_blocks, 256>>>(b2, 1);
    // layer 3
    gemm_kernel<<<gemm_blocks, 256, 98304>>>(nullptr, W3, N_NODES);
    aggregate_kernel<<<agg_blocks, 256>>>(b3, 0);

    pool_kernel<<<N_GRAPHS, HID>>>();
    centroid_kernel<<<N_GRAPHS, HID>>>(cent, ac_temp, out);
}

// round 3
// speedup vs baseline: 1.0808x; 1.0808x over previous
#include <cuda_runtime.h>
#include <cuda_bf16.h>
#include <cstdint>
#include <math.h>

#define N_NODES   100000
#define N_EDGES   1600000
#define HID       128
#define N_CLASSES 18
#define N_CENT    2
#define N_GRAPHS  512

// ---------------- scratch (static device memory; no allocs allowed) ----------
__device__ float g_hn [N_NODES * HID];     // h * dinv  (gather source)
__device__ float g_cur[N_NODES * HID];     // layer output / next layer input
__device__ float g_dinv[N_NODES];
__device__ int   g_deg [N_NODES];          // in-degree (w/o self loop)
__device__ int   g_off [N_NODES];          // CSR row offsets
__device__ int   g_cursor[N_NODES];        // mutable cursor for CSR fill
__device__ int   g_src [N_EDGES];
__device__ int   g_dst [N_EDGES];
__device__ int   g_csr [N_EDGES];          // src indices grouped by dst
__device__ int   g_goff[N_GRAPHS + 1];
__device__ float g_pool[N_GRAPHS * HID];
__device__ __nv_bfloat16 g_wth[HID * HID]; // W^T hi  [N][K] bf16
__device__ __nv_bfloat16 g_wtl[HID * HID]; // W^T lo residual [N][K] bf16
__device__ int   g_eis64;
__device__ int   g_bis64;

// ---------------- setup kernels ---------------------------------------------
__global__ void zero_kernel() {
    int i = blockIdx.x * blockDim.x + threadIdx.x;
    if (i < N_NODES) g_deg[i] = 0;
}

// Detect whether index buffers are int64 or int32 (JAX may silently downcast).
__global__ void detect_kernel(const void* ebuf, const void* bbuf) {
    __shared__ int nz_e, nz_b;
    if (threadIdx.x == 0) { nz_e = 0; nz_b = 0; }
    __syncthreads();
    const int* e32 = (const int*)ebuf;
    const int* b32 = (const int*)bbuf;
    int i = threadIdx.x;
    long long ke = 1000 + (long long)i * 997;
    if (e32[2 * ke + 1] != 0) atomicAdd(&nz_e, 1);
    long long kb = 20000 + (long long)i * 117;
    if (b32[2 * kb + 1] != 0) atomicAdd(&nz_b, 1);
    __syncthreads();
    if (threadIdx.x == 0) { g_eis64 = (nz_e < 8); g_bis64 = (nz_b < 8); }
}

__global__ void convert_edges(const void* ebuf) {
    int e = blockIdx.x * blockDim.x + threadIdx.x;
    if (e >= N_EDGES) return;
    int s, d;
    if (g_eis64) {
        const long long* p = (const long long*)ebuf;
        s = (int)p[e]; d = (int)p[N_EDGES + e];
    } else {
        const int* p = (const int*)ebuf;
        s = p[e]; d = p[N_EDGES + e];
    }
    g_src[e] = s; g_dst[e] = d;
    atomicAdd(&g_deg[d], 1);
}

// batch is sorted -> graph offsets by boundary detection (no atomics, no scan)
__global__ void batch_bounds_kernel(const void* bbuf) {
    int i = blockIdx.x * blockDim.x + threadIdx.x;
    if (i > N_NODES) return;
    int bi = N_GRAPHS, bp = -1;
    if (g_bis64) {
        const long long* p = (const long long*)bbuf;
        if (i < N_NODES) bi = (int)p[i];
        if (i > 0)       bp = (int)p[i - 1];
    } else {
        const int* p = (const int*)bbuf;
        if (i < N_NODES) bi = p[i];
        if (i > 0)       bp = p[i - 1];
    }
    for (int g = bp + 1; g <= bi; g++) g_goff[g] = i;
}

// single-block scan over node degrees -> CSR offsets + cursor copy
#define SCAN_T 1024
#define CHUNK  98
__global__ void node_scan_kernel() {
    __shared__ int wsum[32];
    int tid = threadIdx.x, lane = tid & 31, wid = tid >> 5;
    int start = tid * CHUNK;
    int csum = 0;
    for (int i = 0; i < CHUNK; i++) {
        int idx = start + i;
        if (idx < N_NODES) csum += g_deg[idx];
    }
    int v = csum;
    #pragma unroll
    for (int o = 1; o < 32; o <<= 1) { int t = __shfl_up_sync(0xffffffffu, v, o); if (lane >= o) v += t; }
    if (lane == 31) wsum[wid] = v;
    __syncthreads();
    if (wid == 0) {
        int w = wsum[lane];
        #pragma unroll
        for (int o = 1; o < 32; o <<= 1) { int t = __shfl_up_sync(0xffffffffu, w, o); if (lane >= o) w += t; }
        wsum[lane] = w;
    }
    __syncthreads();
    int run = v - csum + (wid > 0 ? wsum[wid - 1] : 0);
    for (int i = 0; i < CHUNK; i++) {
        int idx = start + i;
        if (idx < N_NODES) {
            g_off[idx] = run;
            g_cursor[idx] = run;
            run += g_deg[idx];
        }
    }
}

__global__ void csr_fill_kernel() {
    int e = blockIdx.x * blockDim.x + threadIdx.x;
    if (e >= N_EDGES) return;
    int d = g_dst[e];
    int pos = atomicAdd(&g_cursor[d], 1);
    g_csr[pos] = g_src[e];
}

__global__ void dinv_kernel() {
    int i = blockIdx.x * blockDim.x + threadIdx.x;
    if (i < N_NODES) g_dinv[i] = rsqrtf((float)g_deg[i] + 1.0f);
}

// ---------------- W transpose + bf16 hi/lo split -----------------------------
__global__ void prep_wt_kernel(const float* __restrict__ W) {
    int i = blockIdx.x * blockDim.x + threadIdx.x;   // 16384
    if (i >= HID * HID) return;
    int k = i >> 7, n = i & 127;
    float w = W[i];                                  // W[k][n]
    __nv_bfloat16 hi = __float2bfloat16_rn(w);
    float rem = w - __bfloat162float(hi);
    g_wth[n * HID + k] = hi;
    g_wtl[n * HID + k] = __float2bfloat16_rn(rem);
}

// ---------------- mma.sync bf16 split GEMM: hn = (X @ W) * dinv[row] ---------
// Block: 128-row x 128-col output tile, 256 threads (8 warps, 16 rows/warp).
// A and W staged in SMEM as bf16 hi/lo, row stride padded to 136 elements
// (272 B = 4-bank shift per row -> conflict-free direct fragment loads).
#define AP 136
#define GEMM_SMEM (4 * 128 * AP * 2)

#define MMA_BF16(c0,c1,c2,c3,a0,a1,a2,a3,b0,b1) \
    asm volatile("mma.sync.aligned.m16n8k16.row.col.f32.bf16.bf16.f32 " \
        "{%0,%1,%2,%3}, {%4,%5,%6,%7}, {%8,%9}, {%0,%1,%2,%3};" \
        : "+f"(c0), "+f"(c1), "+f"(c2), "+f"(c3) \
        : "r"(a0), "r"(a1), "r"(a2), "r"(a3), "r"(b0), "r"(b1))

static __device__ __forceinline__ uint32_t pack_bf2(__nv_bfloat16 lo, __nv_bfloat16 hi) {
    return (uint32_t)__bfloat16_as_ushort(lo) | ((uint32_t)__bfloat16_as_ushort(hi) << 16);
}

__global__ void __launch_bounds__(256, 1)
gemm_mma_kernel(const float* __restrict__ Xin, int n) {
    extern __shared__ __nv_bfloat16 sm[];
    __nv_bfloat16* sAh = sm;
    __nv_bfloat16* sAl = sm + 128 * AP;
    __nv_bfloat16* sWh = sm + 2 * 128 * AP;
    __nv_bfloat16* sWl = sm + 3 * 128 * AP;
    const float* X = Xin ? Xin : g_cur;
    int tid = threadIdx.x;
    int wid = tid >> 5, lane = tid & 31;
    int r0 = blockIdx.x * 128;

    // ---- stage W (pre-split bf16 [N][K]) : 2 threads per row, 32 u32 each --
    {
        int row = tid >> 1, half = tid & 1;
        const uint32_t* srcH = (const uint32_t*)(g_wth + row * HID) + half * 32;
        const uint32_t* srcL = (const uint32_t*)(g_wtl + row * HID) + half * 32;
        uint32_t* dstH = (uint32_t*)(sWh + row * AP) + half * 32;
        uint32_t* dstL = (uint32_t*)(sWl + row * AP) + half * 32;
        #pragma unroll
        for (int j = 0; j < 32; j++) { dstH[j] = srcH[j]; dstL[j] = srcL[j]; }
    }

    // ---- stage A with hi/lo split: 2 threads per row, 16 float4 each --------
    {
        int r = tid >> 1, half = tid & 1;
        int row = r0 + r;
        const float4* src = (const float4*)(X + (size_t)row * HID) + half * 16;
        uint32_t* dstH = (uint32_t*)(sAh + r * AP) + half * 32;
        uint32_t* dstL = (uint32_t*)(sAl + r * AP) + half * 32;
        #pragma unroll
        for (int j = 0; j < 16; j++) {
            float4 v = make_float4(0.f, 0.f, 0.f, 0.f);
            if (row < n) v = src[j];
            __nv_bfloat16 hx = __float2bfloat16_rn(v.x);
            __nv_bfloat16 hy = __float2bfloat16_rn(v.y);
            __nv_bfloat16 hz = __float2bfloat16_rn(v.z);
            __nv_bfloat16 hw = __float2bfloat16_rn(v.w);
            __nv_bfloat16 lx = __float2bfloat16_rn(v.x - __bfloat162float(hx));
            __nv_bfloat16 ly = __float2bfloat16_rn(v.y - __bfloat162float(hy));
            __nv_bfloat16 lz = __float2bfloat16_rn(v.z - __bfloat162float(hz));
            __nv_bfloat16 lw = __float2bfloat16_rn(v.w - __bfloat162float(hw));
            dstH[j * 2 + 0] = pack_bf2(hx, hy);
            dstH[j * 2 + 1] = pack_bf2(hz, hw);
            dstL[j * 2 + 0] = pack_bf2(lx, ly);
            dstL[j * 2 + 1] = pack_bf2(lz, lw);
        }
    }
    __syncthreads();

    // ---- mma mainloop: warp handles rows [wid*16, wid*16+16), all 128 cols --
    float acc[16][4];
    #pragma unroll
    for (int t = 0; t < 16; t++)
        #pragma unroll
        for (int q = 0; q < 4; q++) acc[t][q] = 0.f;

    int arow = wid * 16 + (lane >> 2);          // fragment row (and +8)
    int koff = (lane & 3) * 2;

    #pragma unroll 1
    for (int ks = 0; ks < 8; ks++) {
        int k = ks * 16;
        const __nv_bfloat16* pAh0 = sAh + arow * AP + k + koff;
        const __nv_bfloat16* pAl0 = sAl + arow * AP + k + koff;
        uint32_t ah0 = *(const uint32_t*)(pAh0);
        uint32_t ah1 = *(const uint32_t*)(pAh0 + 8 * AP);
        uint32_t ah2 = *(const uint32_t*)(pAh0 + 8);
        uint32_t ah3 = *(const uint32_t*)(pAh0 + 8 * AP + 8);
        uint32_t al0 = *(const uint32_t*)(pAl0);
        uint32_t al1 = *(const uint32_t*)(pAl0 + 8 * AP);
        uint32_t al2 = *(const uint32_t*)(pAl0 + 8);
        uint32_t al3 = *(const uint32_t*)(pAl0 + 8 * AP + 8);
        #pragma unroll
        for (int nt = 0; nt < 16; nt++) {
            int brow = nt * 8 + (lane >> 2);
            const __nv_bfloat16* pBh = sWh + brow * AP + k + koff;
            const __nv_bfloat16* pBl = sWl + brow * AP + k + koff;
            uint32_t bh0 = *(const uint32_t*)(pBh);
            uint32_t bh1 = *(const uint32_t*)(pBh + 8);
            uint32_t bl0 = *(const uint32_t*)(pBl);
            uint32_t bl1 = *(const uint32_t*)(pBl + 8);
            MMA_BF16(acc[nt][0], acc[nt][1], acc[nt][2], acc[nt][3],
                     ah0, ah1, ah2, ah3, bh0, bh1);
            MMA_BF16(acc[nt][0], acc[nt][1], acc[nt][2], acc[nt][3],
                     ah0, ah1, ah2, ah3, bl0, bl1);
            MMA_BF16(acc[nt][0], acc[nt][1], acc[nt][2], acc[nt][3],
                     al0, al1, al2, al3, bh0, bh1);
        }
    }

    // ---- epilogue: scale by dinv, write g_hn ---------------------------------
    int row0 = r0 + wid * 16 + (lane >> 2);     // rows for c0,c1
    int row1 = row0 + 8;                         // rows for c2,c3
    float di0 = (row0 < n) ? g_dinv[row0] : 0.f;
    float di1 = (row1 < n) ? g_dinv[row1] : 0.f;
    int colb = (lane & 3) * 2;
    #pragma unroll
    for (int nt = 0; nt < 16; nt++) {
        int col = nt * 8 + colb;
        if (row0 < n) {
            float2 v = make_float2(acc[nt][0] * di0, acc[nt][1] * di0);
            *(float2*)(g_hn + (size_t)row0 * HID + col) = v;
        }
        if (row1 < n) {
            float2 v = make_float2(acc[nt][2] * di1, acc[nt][3] * di1);
            *(float2*)(g_hn + (size_t)row1 * HID + col) = v;
        }
    }
}

// ---------------- aggregate: out = dinv[d]*(hn[d]+sum hn[src]) + b (+relu) --
__global__ void aggregate_kernel(const float* __restrict__ bias, int do_relu) {
    int w = (blockIdx.x * blockDim.x + threadIdx.x) >> 5;
    if (w >= N_NODES) return;
    int lane = threadIdx.x & 31;
    const float4* hn4 = (const float4*)g_hn;

    float4 sum = hn4[(size_t)w * 32 + lane];   // self loop: + hn[d]
    int base = g_off[w];
    int cnt  = g_deg[w];
    int j = 0;
    for (; j + 4 <= cnt; j += 4) {
        int s0 = g_csr[base + j + 0];
        int s1 = g_csr[base + j + 1];
        int s2 = g_csr[base + j + 2];
        int s3 = g_csr[base + j + 3];
        float4 v0 = hn4[(size_t)s0 * 32 + lane];
        float4 v1 = hn4[(size_t)s1 * 32 + lane];
        float4 v2 = hn4[(size_t)s2 * 32 + lane];
        float4 v3 = hn4[(size_t)s3 * 32 + lane];
        sum.x += v0.x + v1.x + v2.x + v3.x;
        sum.y += v0.y + v1.y + v2.y + v3.y;
        sum.z += v0.z + v1.z + v2.z + v3.z;
        sum.w += v0.w + v1.w + v2.w + v3.w;
    }
    for (; j < cnt; j++) {
        int s = g_csr[base + j];
        float4 v = hn4[(size_t)s * 32 + lane];
        sum.x += v.x; sum.y += v.y; sum.z += v.z; sum.w += v.w;
    }

    float di = g_dinv[w];
    float4 bv = ((const float4*)bias)[lane];
    float4 o = make_float4(sum.x * di + bv.x, sum.y * di + bv.y,
                           sum.z * di + bv.z, sum.w * di + bv.w);
    if (do_relu) {
        o.x = fmaxf(o.x, 0.f); o.y = fmaxf(o.y, 0.f);
        o.z = fmaxf(o.z, 0.f); o.w = fmaxf(o.w, 0.f);
    }
    ((float4*)g_cur)[(size_t)w * 32 + lane] = o;
}

// ---------------- pooling + centroid head ----------------------------------
__global__ void pool_kernel() {   // block per graph, 128 threads
    int g = blockIdx.x, c = threadIdx.x;
    int s = g_goff[g], e = g_goff[g + 1];
    float sum = 0.f;
    for (int r = s; r < e; r++) sum += g_cur[(size_t)r * HID + c];
    float cntf = (float)(e - s);
    g_pool[g * HID + c] = sum / fmaxf(cntf, 1.0f);
}

__global__ void centroid_kernel(const float* __restrict__ cent,
                                const float* __restrict__ ac_temp,
                                float* __restrict__ out) {
    int b = blockIdx.x;
    int tid = threadIdx.x;            // 128 threads
    int lane = tid & 31, w = tid >> 5;
    __shared__ float sd[N_CLASSES * N_CENT];
    __shared__ float sg[HID];
    sg[tid] = g_pool[b * HID + tid];
    __syncthreads();
    for (int p = w; p < N_CLASSES * N_CENT; p += 4) {
        const float* cp = cent + p * HID;
        float s = 0.f;
        #pragma unroll
        for (int q = 0; q < 4; q++) {
            float d = cp[lane + q * 32] - sg[lane + q * 32];
            s = fmaf(d, d, s);
        }
        #pragma unroll
        for (int o = 16; o; o >>= 1) s += __shfl_xor_sync(0xffffffffu, s, o);
        if (lane == 0) sd[p] = sqrtf(s);
    }
    __syncthreads();
    if (tid == 0) {
        float mind = 1e30f;
        #pragma unroll
        for (int c = 0; c < N_CLASSES; c++) {
            float d = fminf(sd[2 * c], sd[2 * c + 1]);
            out[b * N_CLASSES + c] = -d;
            mind = fminf(mind, d);
        }
        // RUNNING_VAR == 0  =>  max_ac == RUNNING_MEAN == 1.0 exactly
        float accept = 1.0f - mind;
        float t = ac_temp[0];
        out[N_GRAPHS * N_CLASSES + b] = 1.0f / (1.0f + expf(-accept / t));
    }
}

// ---------------- launch ----------------------------------------------------
extern "C" void kernel_launch(void* const* d_in, const int* in_sizes, int n_in,
                              void* d_out, int out_size) {
    const float* x     = (const float*)d_in[0];
    const void*  edges = d_in[1];
    const void*  batch = d_in[2];
    const float* W1 = (const float*)d_in[3];
    const float* b1 = (const float*)d_in[4];
    const float* W2 = (const float*)d_in[5];
    const float* b2 = (const float*)d_in[6];
    const float* W3 = (const float*)d_in[7];
    const float* b3 = (const float*)d_in[8];
    const float* cent = (const float*)d_in[9];
    const float* ac_temp = (const float*)d_in[11];
    float* out = (float*)d_out;

    cudaFuncSetAttribute(gemm_mma_kernel, cudaFuncAttributeMaxDynamicSharedMemorySize, GEMM_SMEM);

    zero_kernel<<<(N_NODES + 255) / 256, 256>>>();
    detect_kernel<<<1, 256>>>(edges, batch);
    convert_edges<<<(N_EDGES + 255) / 256, 256>>>(edges);
    batch_bounds_kernel<<<(N_NODES + 256) / 256, 256>>>(batch);
    node_scan_kernel<<<1, SCAN_T>>>();
    csr_fill_kernel<<<(N_EDGES + 255) / 256, 256>>>();
    dinv_kernel<<<(N_NODES + 255) / 256, 256>>>();

    int gemm_blocks = (N_NODES + 127) / 128;
    int agg_blocks  = (N_NODES * 32 + 255) / 256;

    // layer 1
    prep_wt_kernel<<<64, 256>>>(W1);
    gemm_mma_kernel<<<gemm_blocks, 256, GEMM_SMEM>>>(x, N_NODES);
    aggregate_kernel<<<agg_blocks, 256>>>(b1, 1);
    // layer 2
    prep_wt_kernel<<<64, 256>>>(W2);
    gemm_mma_kernel<<<gemm_blocks, 256, GEMM_SMEM>>>(nullptr, N_NODES);
    aggregate_kernel<<<agg_blocks, 256>>>(b2, 1);
    // layer 3
    prep_wt_kernel<<<64, 256>>>(W3);
    gemm_mma_kernel<<<gemm_blocks, 256, GEMM_SMEM>>>(nullptr, N_NODES);
    aggregate_kernel<<<agg_blocks, 256>>>(b3, 0);

    pool_kernel<<<N_GRAPHS, HID>>>();
    centroid_kernel<<<N_GRAPHS, HID>>>(cent, ac_temp, out);
}

// round 4
// speedup vs baseline: 1.2083x; 1.1180x over previous
#include <cuda_runtime.h>
#include <cuda_bf16.h>
#include <cstdint>
#include <math.h>

#define N_NODES   100000
#define N_EDGES   1600000
#define HID       128
#define N_CLASSES 18
#define N_CENT    2
#define N_GRAPHS  512

// ---------------- scratch (static device memory; no allocs allowed) ----------
__device__ float g_hn [N_NODES * HID];     // h * dinv  (gather source)
__device__ float g_cur[N_NODES * HID];     // layer output / next layer input
__device__ float g_dinv[N_NODES];
__device__ int   g_deg [N_NODES];          // in-degree (w/o self loop)
__device__ int   g_off [N_NODES];          // CSR row offsets
__device__ int   g_cursor[N_NODES];        // mutable cursor for CSR fill
__device__ int   g_csr [N_EDGES];          // src indices grouped by dst
__device__ int   g_goff[N_GRAPHS + 1];
__device__ float g_pool[N_GRAPHS * HID];
__device__ __nv_bfloat16 g_wth[3 * HID * HID]; // W^T hi  [layer][N][K] bf16
__device__ __nv_bfloat16 g_wtl[3 * HID * HID]; // W^T lo residual

// ---------------- local int64/int32 detection (pure, per-block) --------------
// For int64 buffers (values in [0,2^31)), every odd 32-bit word is 0.
// Sample positions chosen so the int32 interpretation is nonzero w.h.p.
static __device__ __forceinline__ int detect_e64(const void* ebuf) {
    const int* p = (const int*)ebuf;
    int nz = 0;
    #pragma unroll
    for (int i = 0; i < 8; i++) {
        long long k = 1000 + (long long)i * 997;
        if (p[2 * k + 1] != 0) nz++;
    }
    return nz < 4;
}
static __device__ __forceinline__ int detect_b64(const void* bbuf) {
    const int* p = (const int*)bbuf;
    int nz = 0;
    #pragma unroll
    for (int i = 0; i < 8; i++) {
        long long k = 20000 + (long long)i * 117;
        if (p[2 * k + 1] != 0) nz++;
    }
    return nz < 4;
}

// ---------------- setup kernels ---------------------------------------------
// zero deg + graph offsets by sorted-batch boundary detection (fused)
__global__ void init_kernel(const void* bbuf) {
    __shared__ int s_b64;
    if (threadIdx.x == 0) s_b64 = detect_b64(bbuf);
    __syncthreads();
    int i = blockIdx.x * blockDim.x + threadIdx.x;
    if (i < N_NODES) g_deg[i] = 0;
    if (i > N_NODES) return;
    int bi = N_GRAPHS, bp = -1;
    if (s_b64) {
        const long long* p = (const long long*)bbuf;
        if (i < N_NODES) bi = (int)p[i];
        if (i > 0)       bp = (int)p[i - 1];
    } else {
        const int* p = (const int*)bbuf;
        if (i < N_NODES) bi = p[i];
        if (i > 0)       bp = p[i - 1];
    }
    for (int g = bp + 1; g <= bi; g++) g_goff[g] = i;
}

__global__ void count_deg_kernel(const void* ebuf) {
    __shared__ int s_e64;
    if (threadIdx.x == 0) s_e64 = detect_e64(ebuf);
    __syncthreads();
    int e = blockIdx.x * blockDim.x + threadIdx.x;
    if (e >= N_EDGES) return;
    int d;
    if (s_e64) d = (int)((const long long*)ebuf)[N_EDGES + e];
    else       d = ((const int*)ebuf)[N_EDGES + e];
    atomicAdd(&g_deg[d], 1);
}

// single-block scan over node degrees -> CSR offsets + cursor + dinv
#define SCAN_T 1024
#define CHUNK  98
__global__ void node_scan_kernel() {
    __shared__ int wsum[32];
    int tid = threadIdx.x, lane = tid & 31, wid = tid >> 5;
    int start = tid * CHUNK;
    int csum = 0;
    for (int i = 0; i < CHUNK; i++) {
        int idx = start + i;
        if (idx < N_NODES) csum += g_deg[idx];
    }
    int v = csum;
    #pragma unroll
    for (int o = 1; o < 32; o <<= 1) { int t = __shfl_up_sync(0xffffffffu, v, o); if (lane >= o) v += t; }
    if (lane == 31) wsum[wid] = v;
    __syncthreads();
    if (wid == 0) {
        int w = wsum[lane];
        #pragma unroll
        for (int o = 1; o < 32; o <<= 1) { int t = __shfl_up_sync(0xffffffffu, w, o); if (lane >= o) w += t; }
        wsum[lane] = w;
    }
    __syncthreads();
    int run = v - csum + (wid > 0 ? wsum[wid - 1] : 0);
    for (int i = 0; i < CHUNK; i++) {
        int idx = start + i;
        if (idx < N_NODES) {
            int d = g_deg[idx];
            g_off[idx] = run;
            g_cursor[idx] = run;
            g_dinv[idx] = rsqrtf((float)d + 1.0f);
            run += d;
        }
    }
}

__global__ void csr_fill_kernel(const void* ebuf) {
    __shared__ int s_e64;
    if (threadIdx.x == 0) s_e64 = detect_e64(ebuf);
    __syncthreads();
    int e = blockIdx.x * blockDim.x + threadIdx.x;
    if (e >= N_EDGES) return;
    int s, d;
    if (s_e64) {
        const long long* p = (const long long*)ebuf;
        s = (int)p[e]; d = (int)p[N_EDGES + e];
    } else {
        const int* p = (const int*)ebuf;
        s = p[e]; d = p[N_EDGES + e];
    }
    int pos = atomicAdd(&g_cursor[d], 1);
    g_csr[pos] = s;
}

// ---------------- W transpose + bf16 hi/lo split, all 3 layers ---------------
__global__ void prep_wt_all_kernel(const float* __restrict__ W1,
                                   const float* __restrict__ W2,
                                   const float* __restrict__ W3) {
    int i = blockIdx.x * blockDim.x + threadIdx.x;   // 3*16384
    if (i >= 3 * HID * HID) return;
    int layer = i >> 14;
    int j = i & (HID * HID - 1);
    int k = j >> 7, n = j & 127;
    const float* W = (layer == 0) ? W1 : (layer == 1) ? W2 : W3;
    float w = W[j];                                  // W[k][n]
    __nv_bfloat16 hi = __float2bfloat16_rn(w);
    float rem = w - __bfloat162float(hi);
    g_wth[layer * HID * HID + n * HID + k] = hi;
    g_wtl[layer * HID * HID + n * HID + k] = __float2bfloat16_rn(rem);
}

// ---------------- mma.sync bf16 split GEMM: hn = (X @ W) * dinv[row] ---------
// Block: 128x128 output tile, 256 threads (8 warps, 16 rows/warp).
// K staged in 2 chunks of 64 -> SMEM 72KB -> 2 blocks/SM.
// Row stride AP=72 bf16 (144B = 36 words; 36 mod 32 = 4 -> 8 rows hit
// distinct banks for fragment loads).
#define AP 72
#define GEMM_SMEM (4 * 128 * AP * 2)

#define MMA_BF16(c0,c1,c2,c3,a0,a1,a2,a3,b0,b1) \
    asm volatile("mma.sync.aligned.m16n8k16.row.col.f32.bf16.bf16.f32 " \
        "{%0,%1,%2,%3}, {%4,%5,%6,%7}, {%8,%9}, {%0,%1,%2,%3};" \
        : "+f"(c0), "+f"(c1), "+f"(c2), "+f"(c3) \
        : "r"(a0), "r"(a1), "r"(a2), "r"(a3), "r"(b0), "r"(b1))

static __device__ __forceinline__ uint32_t pack_bf2(__nv_bfloat16 lo, __nv_bfloat16 hi) {
    return (uint32_t)__bfloat16_as_ushort(lo) | ((uint32_t)__bfloat16_as_ushort(hi) << 16);
}

__global__ void __launch_bounds__(256, 2)
gemm_mma_kernel(const float* __restrict__ Xin,
                const __nv_bfloat16* __restrict__ wth,
                const __nv_bfloat16* __restrict__ wtl, int n) {
    extern __shared__ __nv_bfloat16 sm[];
    __nv_bfloat16* sAh = sm;
    __nv_bfloat16* sAl = sm + 128 * AP;
    __nv_bfloat16* sWh = sm + 2 * 128 * AP;
    __nv_bfloat16* sWl = sm + 3 * 128 * AP;
    const float* X = Xin ? Xin : g_cur;
    int tid = threadIdx.x;
    int wid = tid >> 5, lane = tid & 31;
    int r0 = blockIdx.x * 128;

    float acc[16][4];
    #pragma unroll
    for (int t = 0; t < 16; t++)
        #pragma unroll
        for (int q = 0; q < 4; q++) acc[t][q] = 0.f;

    int arow = wid * 16 + (lane >> 2);
    int koff = (lane & 3) * 2;

    #pragma unroll 1
    for (int ch = 0; ch < 2; ch++) {
        int kbase = ch * 64;
        // ---- stage: warp handles rows wid*16..wid*16+15, fully coalesced ----
        #pragma unroll
        for (int rr = 0; rr < 16; rr++) {
            int r = wid * 16 + rr;
            int row = r0 + r;
            float2 v = make_float2(0.f, 0.f);
            if (row < n) v = *(const float2*)(X + (size_t)row * HID + kbase + lane * 2);
            __nv_bfloat16 hx = __float2bfloat16_rn(v.x);
            __nv_bfloat16 hy = __float2bfloat16_rn(v.y);
            __nv_bfloat16 lx = __float2bfloat16_rn(v.x - __bfloat162float(hx));
            __nv_bfloat16 ly = __float2bfloat16_rn(v.y - __bfloat162float(hy));
            ((uint32_t*)(sAh + r * AP))[lane] = pack_bf2(hx, hy);
            ((uint32_t*)(sAl + r * AP))[lane] = pack_bf2(lx, ly);
            ((uint32_t*)(sWh + r * AP))[lane] =
                ((const uint32_t*)(wth + r * HID + kbase))[lane];
            ((uint32_t*)(sWl + r * AP))[lane] =
                ((const uint32_t*)(wtl + r * HID + kbase))[lane];
        }
        __syncthreads();

        #pragma unroll
        for (int ks = 0; ks < 4; ks++) {
            int k = ks * 16;
            const __nv_bfloat16* pAh0 = sAh + arow * AP + k + koff;
            const __nv_bfloat16* pAl0 = sAl + arow * AP + k + koff;
            uint32_t ah0 = *(const uint32_t*)(pAh0);
            uint32_t ah1 = *(const uint32_t*)(pAh0 + 8 * AP);
            uint32_t ah2 = *(const uint32_t*)(pAh0 + 8);
            uint32_t ah3 = *(const uint32_t*)(pAh0 + 8 * AP + 8);
            uint32_t al0 = *(const uint32_t*)(pAl0);
            uint32_t al1 = *(const uint32_t*)(pAl0 + 8 * AP);
            uint32_t al2 = *(const uint32_t*)(pAl0 + 8);
            uint32_t al3 = *(const uint32_t*)(pAl0 + 8 * AP + 8);
            #pragma unroll
            for (int nt = 0; nt < 16; nt++) {
                int brow = nt * 8 + (lane >> 2);
                const __nv_bfloat16* pBh = sWh + brow * AP + k + koff;
                const __nv_bfloat16* pBl = sWl + brow * AP + k + koff;
                uint32_t bh0 = *(const uint32_t*)(pBh);
                uint32_t bh1 = *(const uint32_t*)(pBh + 8);
                uint32_t bl0 = *(const uint32_t*)(pBl);
                uint32_t bl1 = *(const uint32_t*)(pBl + 8);
                MMA_BF16(acc[nt][0], acc[nt][1], acc[nt][2], acc[nt][3],
                         ah0, ah1, ah2, ah3, bh0, bh1);
                MMA_BF16(acc[nt][0], acc[nt][1], acc[nt][2], acc[nt][3],
                         ah0, ah1, ah2, ah3, bl0, bl1);
                MMA_BF16(acc[nt][0], acc[nt][1], acc[nt][2], acc[nt][3],
                         al0, al1, al2, al3, bh0, bh1);
            }
        }
        __syncthreads();
    }

    // ---- epilogue: scale by dinv, write g_hn ---------------------------------
    int row0 = r0 + wid * 16 + (lane >> 2);
    int row1 = row0 + 8;
    float di0 = (row0 < n) ? g_dinv[row0] : 0.f;
    float di1 = (row1 < n) ? g_dinv[row1] : 0.f;
    int colb = (lane & 3) * 2;
    #pragma unroll
    for (int nt = 0; nt < 16; nt++) {
        int col = nt * 8 + colb;
        if (row0 < n) {
            float2 v = make_float2(acc[nt][0] * di0, acc[nt][1] * di0);
            *(float2*)(g_hn + (size_t)row0 * HID + col) = v;
        }
        if (row1 < n) {
            float2 v = make_float2(acc[nt][2] * di1, acc[nt][3] * di1);
            *(float2*)(g_hn + (size_t)row1 * HID + col) = v;
        }
    }
}

// ---------------- aggregate: out = dinv[d]*(hn[d]+sum hn[src]) + b (+relu) --
// persistent grid, warp-stride over nodes, unroll-8 gather
#define AGG_BLOCKS 1184
__global__ void aggregate_kernel(const float* __restrict__ bias, int do_relu) {
    int lane = threadIdx.x & 31;
    int wstride = (gridDim.x * blockDim.x) >> 5;
    const float4* hn4 = (const float4*)g_hn;
    float4 bv = ((const float4*)bias)[lane];

    for (int w = (blockIdx.x * blockDim.x + threadIdx.x) >> 5; w < N_NODES; w += wstride) {
        float4 sum = hn4[(size_t)w * 32 + lane];   // self loop
        int base = g_off[w];
        int cnt  = g_deg[w];
        int j = 0;
        for (; j + 8 <= cnt; j += 8) {
            int s0 = g_csr[base + j + 0];
            int s1 = g_csr[base + j + 1];
            int s2 = g_csr[base + j + 2];
            int s3 = g_csr[base + j + 3];
            int s4 = g_csr[base + j + 4];
            int s5 = g_csr[base + j + 5];
            int s6 = g_csr[base + j + 6];
            int s7 = g_csr[base + j + 7];
            float4 v0 = hn4[(size_t)s0 * 32 + lane];
            float4 v1 = hn4[(size_t)s1 * 32 + lane];
            float4 v2 = hn4[(size_t)s2 * 32 + lane];
            float4 v3 = hn4[(size_t)s3 * 32 + lane];
            float4 v4 = hn4[(size_t)s4 * 32 + lane];
            float4 v5 = hn4[(size_t)s5 * 32 + lane];
            float4 v6 = hn4[(size_t)s6 * 32 + lane];
            float4 v7 = hn4[(size_t)s7 * 32 + lane];
            sum.x += ((v0.x + v1.x) + (v2.x + v3.x)) + ((v4.x + v5.x) + (v6.x + v7.x));
            sum.y += ((v0.y + v1.y) + (v2.y + v3.y)) + ((v4.y + v5.y) + (v6.y + v7.y));
            sum.z += ((v0.z + v1.z) + (v2.z + v3.z)) + ((v4.z + v5.z) + (v6.z + v7.z));
            sum.w += ((v0.w + v1.w) + (v2.w + v3.w)) + ((v4.w + v5.w) + (v6.w + v7.w));
        }
        for (; j + 2 <= cnt; j += 2) {
            int s0 = g_csr[base + j + 0];
            int s1 = g_csr[base + j + 1];
            float4 v0 = hn4[(size_t)s0 * 32 + lane];
            float4 v1 = hn4[(size_t)s1 * 32 + lane];
            sum.x += v0.x + v1.x; sum.y += v0.y + v1.y;
            sum.z += v0.z + v1.z; sum.w += v0.w + v1.w;
        }
        if (j < cnt) {
            int s = g_csr[base + j];
            float4 v = hn4[(size_t)s * 32 + lane];
            sum.x += v.x; sum.y += v.y; sum.z += v.z; sum.w += v.w;
        }

        float di = g_dinv[w];
        float4 o = make_float4(sum.x * di + bv.x, sum.y * di + bv.y,
                               sum.z * di + bv.z, sum.w * di + bv.w);
        if (do_relu) {
            o.x = fmaxf(o.x, 0.f); o.y = fmaxf(o.y, 0.f);
            o.z = fmaxf(o.z, 0.f); o.w = fmaxf(o.w, 0.f);
        }
        ((float4*)g_cur)[(size_t)w * 32 + lane] = o;
    }
}

// ---------------- pooling + centroid head ----------------------------------
__global__ void pool_kernel() {   // block per graph, 128 threads
    int g = blockIdx.x, c = threadIdx.x;
    int s = g_goff[g], e = g_goff[g + 1];
    float sum = 0.f;
    for (int r = s; r < e; r++) sum += g_cur[(size_t)r * HID + c];
    float cntf = (float)(e - s);
    g_pool[g * HID + c] = sum / fmaxf(cntf, 1.0f);
}

__global__ void centroid_kernel(const float* __restrict__ cent,
                                const float* __restrict__ ac_temp,
                                float* __restrict__ out) {
    int b = blockIdx.x;
    int tid = threadIdx.x;            // 128 threads
    int lane = tid & 31, w = tid >> 5;
    __shared__ float sd[N_CLASSES * N_CENT];
    __shared__ float sg[HID];
    sg[tid] = g_pool[b * HID + tid];
    __syncthreads();
    for (int p = w; p < N_CLASSES * N_CENT; p += 4) {
        const float* cp = cent + p * HID;
        float s = 0.f;
        #pragma unroll
        for (int q = 0; q < 4; q++) {
            float d = cp[lane + q * 32] - sg[lane + q * 32];
            s = fmaf(d, d, s);
        }
        #pragma unroll
        for (int o = 16; o; o >>= 1) s += __shfl_xor_sync(0xffffffffu, s, o);
        if (lane == 0) sd[p] = sqrtf(s);
    }
    __syncthreads();
    if (tid == 0) {
        float mind = 1e30f;
        #pragma unroll
        for (int c = 0; c < N_CLASSES; c++) {
            float d = fminf(sd[2 * c], sd[2 * c + 1]);
            out[b * N_CLASSES + c] = -d;
            mind = fminf(mind, d);
        }
        // RUNNING_VAR == 0  =>  max_ac == RUNNING_MEAN == 1.0 exactly
        float accept = 1.0f - mind;
        float t = ac_temp[0];
        out[N_GRAPHS * N_CLASSES + b] = 1.0f / (1.0f + expf(-accept / t));
    }
}

// ---------------- launch ----------------------------------------------------
extern "C" void kernel_launch(void* const* d_in, const int* in_sizes, int n_in,
                              void* d_out, int out_size) {
    const float* x     = (const float*)d_in[0];
    const void*  edges = d_in[1];
    const void*  batch = d_in[2];
    const float* W1 = (const float*)d_in[3];
    const float* b1 = (const float*)d_in[4];
    const float* W2 = (const float*)d_in[5];
    const float* b2 = (const float*)d_in[6];
    const float* W3 = (const float*)d_in[7];
    const float* b3 = (const float*)d_in[8];
    const float* cent = (const float*)d_in[9];
    const float* ac_temp = (const float*)d_in[11];
    float* out = (float*)d_out;

    cudaFuncSetAttribute(gemm_mma_kernel, cudaFuncAttributeMaxDynamicSharedMemorySize, GEMM_SMEM);

    // device pointers to __device__ weight buffers (resolved host-side once per launch)
    __nv_bfloat16 *wth_p, *wtl_p;
    cudaGetSymbolAddress((void**)&wth_p, g_wth);
    cudaGetSymbolAddress((void**)&wtl_p, g_wtl);

    init_kernel<<<(N_NODES + 256) / 256, 256>>>(batch);
    count_deg_kernel<<<(N_EDGES + 255) / 256, 256>>>(edges);
    node_scan_kernel<<<1, SCAN_T>>>();
    csr_fill_kernel<<<(N_EDGES + 255) / 256, 256>>>(edges);
    prep_wt_all_kernel<<<192, 256>>>(W1, W2, W3);

    int gemm_blocks = (N_NODES + 127) / 128;

    // layer 1
    gemm_mma_kernel<<<gemm_blocks, 256, GEMM_SMEM>>>(x, wth_p, wtl_p, N_NODES);
    aggregate_kernel<<<AGG_BLOCKS, 256>>>(b1, 1);
    // layer 2
    gemm_mma_kernel<<<gemm_blocks, 256, GEMM_SMEM>>>(nullptr, wth_p + HID * HID, wtl_p + HID * HID, N_NODES);
    aggregate_kernel<<<AGG_BLOCKS, 256>>>(b2, 1);
    // layer 3
    gemm_mma_kernel<<<gemm_blocks, 256, GEMM_SMEM>>>(nullptr, wth_p + 2 * HID * HID, wtl_p + 2 * HID * HID, N_NODES);
    aggregate_kernel<<<AGG_BLOCKS, 256>>>(b3, 0);

    pool_kernel<<<N_GRAPHS, HID>>>();
    centroid_kernel<<<N_GRAPHS, HID>>>(cent, ac_temp, out);
}

// round 5
// speedup vs baseline: 1.2913x; 1.0687x over previous
#include <cuda_runtime.h>
#include <cuda_bf16.h>
#include <cuda_fp16.h>
#include <cstdint>
#include <math.h>

#define N_NODES   100000
#define N_EDGES   1600000
#define HID       128
#define N_CLASSES 18
#define N_CENT    2
#define N_GRAPHS  512

// ---------------- scratch (static device memory; no allocs allowed) ----------
__device__ __half g_hn [N_NODES * HID];    // h * dinv, fp16 (gather source)
__device__ float g_cur[N_NODES * HID];     // layer output / next layer input (fp32)
__device__ float g_dinv[N_NODES];
__device__ int   g_deg [N_NODES];          // in-degree (w/o self loop)
__device__ int   g_off [N_NODES];          // CSR row offsets
__device__ int   g_cursor[N_NODES];        // mutable cursor for CSR fill
__device__ int   g_csr [N_EDGES];          // src indices grouped by dst
__device__ int   g_goff[N_GRAPHS + 1];
__device__ float g_pool[N_GRAPHS * HID];
__device__ __nv_bfloat16 g_wth[3 * HID * HID]; // W^T hi  [layer][N][K] bf16
__device__ __nv_bfloat16 g_wtl[3 * HID * HID]; // W^T lo residual

// ---------------- local int64/int32 detection (pure, per-block) --------------
static __device__ __forceinline__ int detect_e64(const void* ebuf) {
    const int* p = (const int*)ebuf;
    int nz = 0;
    #pragma unroll
    for (int i = 0; i < 8; i++) {
        long long k = 1000 + (long long)i * 997;
        if (p[2 * k + 1] != 0) nz++;
    }
    return nz < 4;
}
static __device__ __forceinline__ int detect_b64(const void* bbuf) {
    const int* p = (const int*)bbuf;
    int nz = 0;
    #pragma unroll
    for (int i = 0; i < 8; i++) {
        long long k = 20000 + (long long)i * 117;
        if (p[2 * k + 1] != 0) nz++;
    }
    return nz < 4;
}

// ---------------- setup kernels ---------------------------------------------
// zero deg + graph offsets by sorted-batch boundary detection (fused)
__global__ void init_kernel(const void* bbuf) {
    __shared__ int s_b64;
    if (threadIdx.x == 0) s_b64 = detect_b64(bbuf);
    __syncthreads();
    int i = blockIdx.x * blockDim.x + threadIdx.x;
    if (i < N_NODES) g_deg[i] = 0;
    if (i > N_NODES) return;
    int bi = N_GRAPHS, bp = -1;
    if (s_b64) {
        const long long* p = (const long long*)bbuf;
        if (i < N_NODES) bi = (int)p[i];
        if (i > 0)       bp = (int)p[i - 1];
    } else {
        const int* p = (const int*)bbuf;
        if (i < N_NODES) bi = p[i];
        if (i > 0)       bp = p[i - 1];
    }
    for (int g = bp + 1; g <= bi; g++) g_goff[g] = i;
}

__global__ void count_deg_kernel(const void* ebuf) {
    __shared__ int s_e64;
    if (threadIdx.x == 0) s_e64 = detect_e64(ebuf);
    __syncthreads();
    int e = blockIdx.x * blockDim.x + threadIdx.x;
    if (e >= N_EDGES) return;
    int d;
    if (s_e64) d = (int)((const long long*)ebuf)[N_EDGES + e];
    else       d = ((const int*)ebuf)[N_EDGES + e];
    atomicAdd(&g_deg[d], 1);
}

// single-block scan over node degrees -> CSR offsets + cursor + dinv
#define SCAN_T 1024
#define CHUNK  98
__global__ void node_scan_kernel() {
    __shared__ int wsum[32];
    int tid = threadIdx.x, lane = tid & 31, wid = tid >> 5;
    int start = tid * CHUNK;
    int csum = 0;
    for (int i = 0; i < CHUNK; i++) {
        int idx = start + i;
        if (idx < N_NODES) csum += g_deg[idx];
    }
    int v = csum;
    #pragma unroll
    for (int o = 1; o < 32; o <<= 1) { int t = __shfl_up_sync(0xffffffffu, v, o); if (lane >= o) v += t; }
    if (lane == 31) wsum[wid] = v;
    __syncthreads();
    if (wid == 0) {
        int w = wsum[lane];
        #pragma unroll
        for (int o = 1; o < 32; o <<= 1) { int t = __shfl_up_sync(0xffffffffu, w, o); if (lane >= o) w += t; }
        wsum[lane] = w;
    }
    __syncthreads();
    int run = v - csum + (wid > 0 ? wsum[wid - 1] : 0);
    for (int i = 0; i < CHUNK; i++) {
        int idx = start + i;
        if (idx < N_NODES) {
            int d = g_deg[idx];
            g_off[idx] = run;
            g_cursor[idx] = run;
            g_dinv[idx] = rsqrtf((float)d + 1.0f);
            run += d;
        }
    }
}

__global__ void csr_fill_kernel(const void* ebuf) {
    __shared__ int s_e64;
    if (threadIdx.x == 0) s_e64 = detect_e64(ebuf);
    __syncthreads();
    int e = blockIdx.x * blockDim.x + threadIdx.x;
    if (e >= N_EDGES) return;
    int s, d;
    if (s_e64) {
        const long long* p = (const long long*)ebuf;
        s = (int)p[e]; d = (int)p[N_EDGES + e];
    } else {
        const int* p = (const int*)ebuf;
        s = p[e]; d = p[N_EDGES + e];
    }
    int pos = atomicAdd(&g_cursor[d], 1);
    g_csr[pos] = s;
}

// ---------------- W transpose + bf16 hi/lo split, all 3 layers ---------------
__global__ void prep_wt_all_kernel(const float* __restrict__ W1,
                                   const float* __restrict__ W2,
                                   const float* __restrict__ W3) {
    int i = blockIdx.x * blockDim.x + threadIdx.x;   // 3*16384
    if (i >= 3 * HID * HID) return;
    int layer = i >> 14;
    int j = i & (HID * HID - 1);
    int k = j >> 7, n = j & 127;
    const float* W = (layer == 0) ? W1 : (layer == 1) ? W2 : W3;
    float w = W[j];                                  // W[k][n]
    __nv_bfloat16 hi = __float2bfloat16_rn(w);
    float rem = w - __bfloat162float(hi);
    g_wth[layer * HID * HID + n * HID + k] = hi;
    g_wtl[layer * HID * HID + n * HID + k] = __float2bfloat16_rn(rem);
}

// ---------------- mma.sync bf16 split GEMM: hn = fp16((X @ W) * dinv) --------
#define AP 72
#define GEMM_SMEM (4 * 128 * AP * 2)

#define MMA_BF16(c0,c1,c2,c3,a0,a1,a2,a3,b0,b1) \
    asm volatile("mma.sync.aligned.m16n8k16.row.col.f32.bf16.bf16.f32 " \
        "{%0,%1,%2,%3}, {%4,%5,%6,%7}, {%8,%9}, {%0,%1,%2,%3};" \
        : "+f"(c0), "+f"(c1), "+f"(c2), "+f"(c3) \
        : "r"(a0), "r"(a1), "r"(a2), "r"(a3), "r"(b0), "r"(b1))

static __device__ __forceinline__ uint32_t pack_bf2(__nv_bfloat16 lo, __nv_bfloat16 hi) {
    return (uint32_t)__bfloat16_as_ushort(lo) | ((uint32_t)__bfloat16_as_ushort(hi) << 16);
}

__global__ void __launch_bounds__(256, 2)
gemm_mma_kernel(const float* __restrict__ Xin,
                const __nv_bfloat16* __restrict__ wth,
                const __nv_bfloat16* __restrict__ wtl, int n) {
    extern __shared__ __nv_bfloat16 sm[];
    __nv_bfloat16* sAh = sm;
    __nv_bfloat16* sAl = sm + 128 * AP;
    __nv_bfloat16* sWh = sm + 2 * 128 * AP;
    __nv_bfloat16* sWl = sm + 3 * 128 * AP;
    const float* X = Xin ? Xin : g_cur;
    int tid = threadIdx.x;
    int wid = tid >> 5, lane = tid & 31;
    int r0 = blockIdx.x * 128;

    float acc[16][4];
    #pragma unroll
    for (int t = 0; t < 16; t++)
        #pragma unroll
        for (int q = 0; q < 4; q++) acc[t][q] = 0.f;

    int arow = wid * 16 + (lane >> 2);
    int koff = (lane & 3) * 2;

    #pragma unroll 1
    for (int ch = 0; ch < 2; ch++) {
        int kbase = ch * 64;
        #pragma unroll
        for (int rr = 0; rr < 16; rr++) {
            int r = wid * 16 + rr;
            int row = r0 + r;
            float2 v = make_float2(0.f, 0.f);
            if (row < n) v = *(const float2*)(X + (size_t)row * HID + kbase + lane * 2);
            __nv_bfloat16 hx = __float2bfloat16_rn(v.x);
            __nv_bfloat16 hy = __float2bfloat16_rn(v.y);
            __nv_bfloat16 lx = __float2bfloat16_rn(v.x - __bfloat162float(hx));
            __nv_bfloat16 ly = __float2bfloat16_rn(v.y - __bfloat162float(hy));
            ((uint32_t*)(sAh + r * AP))[lane] = pack_bf2(hx, hy);
            ((uint32_t*)(sAl + r * AP))[lane] = pack_bf2(lx, ly);
            ((uint32_t*)(sWh + r * AP))[lane] =
                ((const uint32_t*)(wth + r * HID + kbase))[lane];
            ((uint32_t*)(sWl + r * AP))[lane] =
                ((const uint32_t*)(wtl + r * HID + kbase))[lane];
        }
        __syncthreads();

        #pragma unroll
        for (int ks = 0; ks < 4; ks++) {
            int k = ks * 16;
            const __nv_bfloat16* pAh0 = sAh + arow * AP + k + koff;
            const __nv_bfloat16* pAl0 = sAl + arow * AP + k + koff;
            uint32_t ah0 = *(const uint32_t*)(pAh0);
            uint32_t ah1 = *(const uint32_t*)(pAh0 + 8 * AP);
            uint32_t ah2 = *(const uint32_t*)(pAh0 + 8);
            uint32_t ah3 = *(const uint32_t*)(pAh0 + 8 * AP + 8);
            uint32_t al0 = *(const uint32_t*)(pAl0);
            uint32_t al1 = *(const uint32_t*)(pAl0 + 8 * AP);
            uint32_t al2 = *(const uint32_t*)(pAl0 + 8);
            uint32_t al3 = *(const uint32_t*)(pAl0 + 8 * AP + 8);
            #pragma unroll
            for (int nt = 0; nt < 16; nt++) {
                int brow = nt * 8 + (lane >> 2);
                const __nv_bfloat16* pBh = sWh + brow * AP + k + koff;
                const __nv_bfloat16* pBl = sWl + brow * AP + k + koff;
                uint32_t bh0 = *(const uint32_t*)(pBh);
                uint32_t bh1 = *(const uint32_t*)(pBh + 8);
                uint32_t bl0 = *(const uint32_t*)(pBl);
                uint32_t bl1 = *(const uint32_t*)(pBl + 8);
                MMA_BF16(acc[nt][0], acc[nt][1], acc[nt][2], acc[nt][3],
                         ah0, ah1, ah2, ah3, bh0, bh1);
                MMA_BF16(acc[nt][0], acc[nt][1], acc[nt][2], acc[nt][3],
                         ah0, ah1, ah2, ah3, bl0, bl1);
                MMA_BF16(acc[nt][0], acc[nt][1], acc[nt][2], acc[nt][3],
                         al0, al1, al2, al3, bh0, bh1);
            }
        }
        __syncthreads();
    }

    // ---- epilogue: scale by dinv (inline from deg), write fp16 g_hn ---------
    int row0 = r0 + wid * 16 + (lane >> 2);
    int row1 = row0 + 8;
    float di0 = (row0 < n) ? rsqrtf((float)g_deg[row0] + 1.0f) : 0.f;
    float di1 = (row1 < n) ? rsqrtf((float)g_deg[row1] + 1.0f) : 0.f;
    int colb = (lane & 3) * 2;
    #pragma unroll
    for (int nt = 0; nt < 16; nt++) {
        int col = nt * 8 + colb;
        if (row0 < n)
            *(__half2*)(g_hn + (size_t)row0 * HID + col) =
                __floats2half2_rn(acc[nt][0] * di0, acc[nt][1] * di0);
        if (row1 < n)
            *(__half2*)(g_hn + (size_t)row1 * HID + col) =
                __floats2half2_rn(acc[nt][2] * di1, acc[nt][3] * di1);
    }
}

// ---------------- aggregate: out = dinv[d]*(hn[d]+sum hn[src]) + b (+relu) --
// fp16 gather (256 B/row), fp32 accumulate; persistent grid, unroll-8
#define AGG_BLOCKS 1184
static __device__ __forceinline__ float4 h4_to_f4(uint2 u) {
    __half2 a = *(__half2*)&u.x;
    __half2 b = *(__half2*)&u.y;
    float2 f0 = __half22float2(a);
    float2 f1 = __half22float2(b);
    return make_float4(f0.x, f0.y, f1.x, f1.y);
}

__global__ void aggregate_kernel(const float* __restrict__ bias, int do_relu) {
    int lane = threadIdx.x & 31;
    int wstride = (gridDim.x * blockDim.x) >> 5;
    const uint2* hn2 = (const uint2*)g_hn;    // 4 halves per lane-slot, 32/row
    float4 bv = ((const float4*)bias)[lane];

    for (int w = (blockIdx.x * blockDim.x + threadIdx.x) >> 5; w < N_NODES; w += wstride) {
        float4 sum = h4_to_f4(hn2[(size_t)w * 32 + lane]);   // self loop
        int base = g_off[w];
        int cnt  = g_deg[w];
        int j = 0;
        for (; j + 8 <= cnt; j += 8) {
            int s0 = g_csr[base + j + 0];
            int s1 = g_csr[base + j + 1];
            int s2 = g_csr[base + j + 2];
            int s3 = g_csr[base + j + 3];
            int s4 = g_csr[base + j + 4];
            int s5 = g_csr[base + j + 5];
            int s6 = g_csr[base + j + 6];
            int s7 = g_csr[base + j + 7];
            float4 v0 = h4_to_f4(hn2[(size_t)s0 * 32 + lane]);
            float4 v1 = h4_to_f4(hn2[(size_t)s1 * 32 + lane]);
            float4 v2 = h4_to_f4(hn2[(size_t)s2 * 32 + lane]);
            float4 v3 = h4_to_f4(hn2[(size_t)s3 * 32 + lane]);
            float4 v4 = h4_to_f4(hn2[(size_t)s4 * 32 + lane]);
            float4 v5 = h4_to_f4(hn2[(size_t)s5 * 32 + lane]);
            float4 v6 = h4_to_f4(hn2[(size_t)s6 * 32 + lane]);
            float4 v7 = h4_to_f4(hn2[(size_t)s7 * 32 + lane]);
            sum.x += ((v0.x + v1.x) + (v2.x + v3.x)) + ((v4.x + v5.x) + (v6.x + v7.x));
            sum.y += ((v0.y + v1.y) + (v2.y + v3.y)) + ((v4.y + v5.y) + (v6.y + v7.y));
            sum.z += ((v0.z + v1.z) + (v2.z + v3.z)) + ((v4.z + v5.z) + (v6.z + v7.z));
            sum.w += ((v0.w + v1.w) + (v2.w + v3.w)) + ((v4.w + v5.w) + (v6.w + v7.w));
        }
        for (; j + 2 <= cnt; j += 2) {
            int s0 = g_csr[base + j + 0];
            int s1 = g_csr[base + j + 1];
            float4 v0 = h4_to_f4(hn2[(size_t)s0 * 32 + lane]);
            float4 v1 = h4_to_f4(hn2[(size_t)s1 * 32 + lane]);
            sum.x += v0.x + v1.x; sum.y += v0.y + v1.y;
            sum.z += v0.z + v1.z; sum.w += v0.w + v1.w;
        }
        if (j < cnt) {
            int s = g_csr[base + j];
            float4 v = h4_to_f4(hn2[(size_t)s * 32 + lane]);
            sum.x += v.x; sum.y += v.y; sum.z += v.z; sum.w += v.w;
        }

        float di = g_dinv[w];
        float4 o = make_float4(sum.x * di + bv.x, sum.y * di + bv.y,
                               sum.z * di + bv.z, sum.w * di + bv.w);
        if (do_relu) {
            o.x = fmaxf(o.x, 0.f); o.y = fmaxf(o.y, 0.f);
            o.z = fmaxf(o.z, 0.f); o.w = fmaxf(o.w, 0.f);
        }
        ((float4*)g_cur)[(size_t)w * 32 + lane] = o;
    }
}

// ---------------- pooling + centroid head ----------------------------------
__global__ void pool_kernel() {   // block per graph, 128 threads
    int g = blockIdx.x, c = threadIdx.x;
    int s = g_goff[g], e = g_goff[g + 1];
    float sum = 0.f;
    for (int r = s; r < e; r++) sum += g_cur[(size_t)r * HID + c];
    float cntf = (float)(e - s);
    g_pool[g * HID + c] = sum / fmaxf(cntf, 1.0f);
}

__global__ void centroid_kernel(const float* __restrict__ cent,
                                const float* __restrict__ ac_temp,
                                float* __restrict__ out) {
    int b = blockIdx.x;
    int tid = threadIdx.x;            // 128 threads
    int lane = tid & 31, w = tid >> 5;
    __shared__ float sd[N_CLASSES * N_CENT];
    __shared__ float sg[HID];
    sg[tid] = g_pool[b * HID + tid];
    __syncthreads();
    for (int p = w; p < N_CLASSES * N_CENT; p += 4) {
        const float* cp = cent + p * HID;
        float s = 0.f;
        #pragma unroll
        for (int q = 0; q < 4; q++) {
            float d = cp[lane + q * 32] - sg[lane + q * 32];
            s = fmaf(d, d, s);
        }
        #pragma unroll
        for (int o = 16; o; o >>= 1) s += __shfl_xor_sync(0xffffffffu, s, o);
        if (lane == 0) sd[p] = sqrtf(s);
    }
    __syncthreads();
    if (tid == 0) {
        float mind = 1e30f;
        #pragma unroll
        for (int c = 0; c < N_CLASSES; c++) {
            float d = fminf(sd[2 * c], sd[2 * c + 1]);
            out[b * N_CLASSES + c] = -d;
            mind = fminf(mind, d);
        }
        // RUNNING_VAR == 0  =>  max_ac == RUNNING_MEAN == 1.0 exactly
        float accept = 1.0f - mind;
        float t = ac_temp[0];
        out[N_GRAPHS * N_CLASSES + b] = 1.0f / (1.0f + expf(-accept / t));
    }
}

// ---------------- launch ----------------------------------------------------
extern "C" void kernel_launch(void* const* d_in, const int* in_sizes, int n_in,
                              void* d_out, int out_size) {
    const float* x     = (const float*)d_in[0];
    const void*  edges = d_in[1];
    const void*  batch = d_in[2];
    const float* W1 = (const float*)d_in[3];
    const float* b1 = (const float*)d_in[4];
    const float* W2 = (const float*)d_in[5];
    const float* b2 = (const float*)d_in[6];
    const float* W3 = (const float*)d_in[7];
    const float* b3 = (const float*)d_in[8];
    const float* cent = (const float*)d_in[9];
    const float* ac_temp = (const float*)d_in[11];
    float* out = (float*)d_out;

    cudaFuncSetAttribute(gemm_mma_kernel, cudaFuncAttributeMaxDynamicSharedMemorySize, GEMM_SMEM);

    __nv_bfloat16 *wth_p, *wtl_p;
    cudaGetSymbolAddress((void**)&wth_p, g_wth);
    cudaGetSymbolAddress((void**)&wtl_p, g_wtl);

    int gemm_blocks = (N_NODES + 127) / 128;

    // Order chosen so launch index 3 (the one ncu samples) is gemm1.
    prep_wt_all_kernel<<<192, 256>>>(W1, W2, W3);              // 0
    init_kernel<<<(N_NODES + 256) / 256, 256>>>(batch);        // 1
    count_deg_kernel<<<(N_EDGES + 255) / 256, 256>>>(edges);   // 2
    gemm_mma_kernel<<<gemm_blocks, 256, GEMM_SMEM>>>(x, wth_p, wtl_p, N_NODES); // 3
    node_scan_kernel<<<1, SCAN_T>>>();                          // 4
    csr_fill_kernel<<<(N_EDGES + 255) / 256, 256>>>(edges);     // 5
    aggregate_kernel<<<AGG_BLOCKS, 256>>>(b1, 1);               // 6

    gemm_mma_kernel<<<gemm_blocks, 256, GEMM_SMEM>>>(nullptr, wth_p + HID * HID, wtl_p + HID * HID, N_NODES);
    aggregate_kernel<<<AGG_BLOCKS, 256>>>(b2, 1);
    gemm_mma_kernel<<<gemm_blocks, 256, GEMM_SMEM>>>(nullptr, wth_p + 2 * HID * HID, wtl_p + 2 * HID * HID, N_NODES);
    aggregate_kernel<<<AGG_BLOCKS, 256>>>(b3, 0);

    pool_kernel<<<N_GRAPHS, HID>>>();
    centroid_kernel<<<N_GRAPHS, HID>>>(cent, ac_temp, out);
}